// round 17
// baseline (speedup 1.0000x reference)
#include <cuda_runtime.h>
#include <cuda_fp16.h>
#include <cstdint>
#include <cmath>

#define I_DIM 512
#define H_DIM 512
#define KTOT  1024
#define NTOT  1024
#define BATCH 65536

// ---------------------------------------------------------------------------
// Device scratch (fp16 single-term operands)
// A2h: u4 index = (rb*64 + kb)*32 + lane      rb: 16-row block, kb: k16 block
// W2h: u4 index = (nb*64 + kb)*32 + lane      nb: 16-col block
// Column interleave on W (2j=tau, 2j+1=f); k-permutation pi on both.
// ---------------------------------------------------------------------------
__device__ uint4  g_A2h[(size_t)4096 * 64 * 32];         // 134 MB
__device__ uint4  g_W2h[(size_t)64 * 64 * 32];           // 2 MB
__device__ float  g_Y[(size_t)BATCH * H_DIM];            // 128 MB (pre-LN y)
__device__ float2 g_Spart[(size_t)BATCH * 8];            // 4 MB (LN partials, per bn)

__device__ __forceinline__ uint32_t smem_u32(const void* p) {
    uint32_t a;
    asm("{ .reg .u64 t; cvta.to.shared.u64 t, %1; cvt.u32.u64 %0, t; }"
        : "=r"(a) : "l"(p));
    return a;
}
__device__ __forceinline__ uint32_t pack_h2(float a, float b) {
    __half2 h = __floats2half2_rn(a, b);
    return *(uint32_t*)&h;
}
__device__ __forceinline__ void mma16816_f16(float* c, const uint4& a,
                                             uint32_t b0, uint32_t b1) {
    asm volatile(
        "mma.sync.aligned.m16n8k16.row.col.f32.f16.f16.f32 "
        "{%0,%1,%2,%3}, {%4,%5,%6,%7}, {%8,%9}, {%0,%1,%2,%3};"
        : "+f"(c[0]), "+f"(c[1]), "+f"(c[2]), "+f"(c[3])
        : "r"(a.x), "r"(a.y), "r"(a.z), "r"(a.w), "r"(b0), "r"(b1));
}
#define CP_ASYNC16(dst, src) \
    asm volatile("cp.async.cg.shared.global [%0], [%1], 16;" \
                 :: "r"(dst), "l"(src) : "memory")
#define CP_COMMIT() asm volatile("cp.async.commit_group;" ::: "memory")
#define CP_WAIT2()  asm volatile("cp.async.wait_group 2;" ::: "memory")
#define CP_WAIT0()  asm volatile("cp.async.wait_group 0;" ::: "memory")
#define LDS128(v, addr) \
    asm volatile("ld.shared.v4.u32 {%0,%1,%2,%3}, [%4];" \
        : "=r"((v).x), "=r"((v).y), "=r"((v).z), "=r"((v).w) : "r"(addr))

// ---------------------------------------------------------------------------
__device__ __forceinline__ float w_at2(const float* W_in, const float* W_rec,
                                       const float* W_tau, int c, int k) {
    int j = c >> 1;
    if ((c & 1) == 0) return W_tau[j * KTOT + k];
    return (k < I_DIM) ? W_in[j * I_DIM + k] : W_rec[j * H_DIM + (k - I_DIM)];
}

// ---------------------------------------------------------------------------
// Combined prep kernel (fp16, pi on both A and W) — unchanged from R15/R16.
// ---------------------------------------------------------------------------
__global__ __launch_bounds__(256)
void prep_kernel(const float* __restrict__ x, const float* __restrict__ h,
                 const float* __restrict__ W_in, const float* __restrict__ W_rec,
                 const float* __restrict__ W_tau) {
    const int tid = threadIdx.x;
    const int lane = tid & 31;

    if (blockIdx.x < 4096) {
        const int rb = blockIdx.x;
        const int wid = tid >> 5;

        const int r0 = lane >> 2;
        const int tg4 = (lane & 3) * 4;
        const size_t rowA = (size_t)rb * 16 + r0;
        const size_t rowB = rowA + 8;

#pragma unroll
        for (int j = 0; j < 8; j++) {
            int kb = wid * 8 + j;
            int kg = kb * 16 + tg4;
            const float* srcA;
            const float* srcB;
            if (kb < 32) { srcA = x + rowA * I_DIM + kg;          srcB = x + rowB * I_DIM + kg; }
            else         { srcA = h + rowA * H_DIM + (kg - 512);  srcB = h + rowB * H_DIM + (kg - 512); }

            float4 va = *(const float4*)srcA;
            float4 vb = *(const float4*)srcB;

            uint4 hi;
            hi.x = pack_h2(va.x, va.y); hi.y = pack_h2(vb.x, vb.y);
            hi.z = pack_h2(va.z, va.w); hi.w = pack_h2(vb.z, vb.w);

            g_A2h[(size_t)(rb * 64 + kb) * 32 + lane] = hi;
        }
    } else {
        int t = (blockIdx.x - 4096) * blockDim.x + tid;
        int idx = t >> 5;
        int kb = idx & 63;
        int nb = idx >> 6;

        int n0 = nb * 16 + (lane >> 2);
        int k0 = kb * 16 + (lane & 3) * 4;

        float v[8];
        v[0] = w_at2(W_in, W_rec, W_tau, n0,     k0);
        v[1] = w_at2(W_in, W_rec, W_tau, n0,     k0 + 1);
        v[2] = w_at2(W_in, W_rec, W_tau, n0,     k0 + 2);
        v[3] = w_at2(W_in, W_rec, W_tau, n0,     k0 + 3);
        v[4] = w_at2(W_in, W_rec, W_tau, n0 + 8, k0);
        v[5] = w_at2(W_in, W_rec, W_tau, n0 + 8, k0 + 1);
        v[6] = w_at2(W_in, W_rec, W_tau, n0 + 8, k0 + 2);
        v[7] = w_at2(W_in, W_rec, W_tau, n0 + 8, k0 + 3);

        uint4 hi;
        hi.x = pack_h2(v[0], v[1]); hi.y = pack_h2(v[2], v[3]);
        hi.z = pack_h2(v[4], v[5]); hi.w = pack_h2(v[6], v[7]);

        g_W2h[(size_t)(nb * 64 + kb) * 32 + lane] = hi;
    }
}

// ---------------------------------------------------------------------------
// fp16 GEMM + smem-staged fused epilogue.
// CTA 128x128, 4 warps, warp tile 64x64 (2x2), BK=32.
// 6-stage cp.async (16KB stages), prefetch distance 4, sync every 2 iters
// (safe: N_STAGES >= D + S = 6; overwritten stage is 2 iters stale, barrier
//  <= 2 iters back).  wait_group(2) at even iters completes groups <= i+1.
// ---------------------------------------------------------------------------
#define STAGE_BYTES 16384
#define N_STAGES 6
#define TPAD 68
#define SMEM_REQ (N_STAGES * STAGE_BYTES)   // 98304 B (tail needs 69632, fits)

__global__ __launch_bounds__(128)
void gemm_mma_kernel(const float* __restrict__ hin,
                     const float* __restrict__ b_in,
                     const float* __restrict__ b_tau,
                     float* __restrict__ out_tau) {
    extern __shared__ char smem[];
    const uint32_t sbase = smem_u32(smem);

    const int tid  = threadIdx.x;
    const int wid  = tid >> 5;            // 0..3
    const int lane = tid & 31;
    const int bn = blockIdx.x;            // 0..7
    const int bm = blockIdx.y;            // 0..511
    const int wm = wid & 1;
    const int wn = wid >> 1;              // 0..1

    // 1024 chunks/stage, 8 per thread (128 threads)
    uint32_t soff[8];
    const uint4* gptr[8];
#pragma unroll
    for (int j = 0; j < 8; j++) {
        int c = tid + j * 128;
        if (c < 512) {
            int cl = c & 31;
            int mb = (c >> 5) & 7;
            int kb = (c >> 8) & 1;
            int rb = bm * 8 + mb;
            gptr[j] = g_A2h + ((size_t)(rb * 64 + kb) * 32 + cl);
            soff[j] = (uint32_t)(c * 16);
        } else {
            int cb = c - 512;
            int cl = cb & 31;
            int nb = (cb >> 5) & 7;
            int kb = (cb >> 8) & 1;
            int nbg = bn * 8 + nb;
            gptr[j] = g_W2h + ((size_t)(nbg * 64 + kb) * 32 + cl);
            soff[j] = (uint32_t)(8192 + cb * 16);
        }
    }

    float acc[4][8][4];
#pragma unroll
    for (int a = 0; a < 4; a++)
#pragma unroll
        for (int b = 0; b < 8; b++)
#pragma unroll
            for (int d = 0; d < 4; d++) acc[a][b][d] = 0.f;

    // prologue: stages 0..3 (prefetch distance 4)
#pragma unroll
    for (int s = 0; s < 4; s++) {
#pragma unroll
        for (int j = 0; j < 8; j++)
            CP_ASYNC16(sbase + s * STAGE_BYTES + soff[j], gptr[j] + (size_t)s * 64);
        CP_COMMIT();
    }

    const int mbB = wm * 4;
    const int nbB = wn * 4;

    // stage index runs mod 6; iteration i uses stage i%6, issues stage (i+4)%6
    int st_rd = 0, st_wr = 4;
    for (int i = 0; i < 32; i++) {
        if ((i & 1) == 0) {
            CP_WAIT2();                   // groups <= i+1 complete
            __syncthreads();
        }

        if (i + 4 < 32) {
            uint32_t sb = sbase + st_wr * STAGE_BYTES;
#pragma unroll
            for (int j = 0; j < 8; j++)
                CP_ASYNC16(sb + soff[j], gptr[j] + (size_t)(i + 4) * 64);
        }
        CP_COMMIT();
        if (++st_wr == N_STAGES) st_wr = 0;

        const uint32_t st = sbase + st_rd * STAGE_BYTES;
        if (++st_rd == N_STAGES) st_rd = 0;
#pragma unroll
        for (int kb = 0; kb < 2; kb++) {
            uint4 ah[4], bh[4];
#pragma unroll
            for (int mt = 0; mt < 4; mt++)
                LDS128(ah[mt], st + (uint32_t)((kb * 8 + mbB + mt) * 512) + lane * 16);
#pragma unroll
            for (int q = 0; q < 4; q++)
                LDS128(bh[q], st + (uint32_t)(8192 + (kb * 8 + nbB + q) * 512) + lane * 16);
#pragma unroll
            for (int mt = 0; mt < 4; mt++) {
#pragma unroll
                for (int nt = 0; nt < 8; nt++) {
                    const uint4& B = bh[nt >> 1];
                    uint32_t b0 = (nt & 1) ? B.z : B.x;
                    uint32_t b1 = (nt & 1) ? B.w : B.y;
                    mma16816_f16(acc[mt][nt], ah[mt], b0, b1);
                }
            }
        }
    }

    // ---- tail: drain pipeline, then reuse smem for staging ----
    CP_WAIT0();
    __syncthreads();

    const uint32_t tauT = sbase;                  // [128][68] float
    const uint32_t fT   = sbase + 128 * TPAD * 4; // [128][68] float
    const int g  = lane >> 2;
    const int tg = lane & 3;

    // Phase 1: scatter raw pre-activations to smem
#pragma unroll
    for (int mt = 0; mt < 4; mt++) {
        int r0 = wm * 64 + mt * 16 + g;
        int r1 = r0 + 8;
#pragma unroll
        for (int nt = 0; nt < 8; nt++) {
            int jj = wn * 32 + nt * 4 + tg;
            asm volatile("st.shared.f32 [%0], %1;" :: "r"(tauT + (uint32_t)(r0 * TPAD + jj) * 4), "f"(acc[mt][nt][0]) : "memory");
            asm volatile("st.shared.f32 [%0], %1;" :: "r"(fT   + (uint32_t)(r0 * TPAD + jj) * 4), "f"(acc[mt][nt][1]) : "memory");
            asm volatile("st.shared.f32 [%0], %1;" :: "r"(tauT + (uint32_t)(r1 * TPAD + jj) * 4), "f"(acc[mt][nt][2]) : "memory");
            asm volatile("st.shared.f32 [%0], %1;" :: "r"(fT   + (uint32_t)(r1 * TPAD + jj) * 4), "f"(acc[mt][nt][3]) : "memory");
        }
    }
    __syncthreads();

    // Phase 2: coalesced writeout, 128 threads: half-warp owns a row, 16 iters.
    const int jj4 = tid & 15;
    const int rgrp = tid >> 4;                    // 0..7
    const int jbase = bn * 64;
    const float4 bt4 = ((const float4*)b_tau)[jbase / 4 + jj4];
    const float4 bi4 = ((const float4*)b_in)[jbase / 4 + jj4];

#pragma unroll
    for (int quarter = 0; quarter < 4; quarter++) {
        float4 h4s[4];
#pragma unroll
        for (int u = 0; u < 4; u++) {
            int r = rgrp + (quarter * 4 + u) * 8;
            size_t row = (size_t)bm * 128 + r;
            h4s[u] = *((const float4*)(hin + row * H_DIM + jbase) + jj4);
        }
#pragma unroll
        for (int u = 0; u < 4; u++) {
            int r = rgrp + (quarter * 4 + u) * 8;
            size_t row = (size_t)bm * 128 + r;

            float4 tp, fp;
            LDS128(*(uint4*)&tp, tauT + (uint32_t)(r * TPAD + jj4 * 4) * 4);
            LDS128(*(uint4*)&fp, fT   + (uint32_t)(r * TPAD + jj4 * 4) * 4);
            float4 h4 = h4s[u];

            float4 tv, yv;
            float s = 0.f, q = 0.f;
            {
                const float* ptp = &tp.x; const float* pfp = &fp.x;
                const float* ph = &h4.x; const float* pbt = &bt4.x; const float* pbi = &bi4.x;
                float* ptv = &tv.x; float* pyv = &yv.x;
#pragma unroll
                for (int c = 0; c < 4; c++) {
                    float tau = 0.5f + 4.5f / (1.0f + __expf(-(ptp[c] + pbt[c])));
                    float f   = tanhf(pfp[c] + pbi[c]);
                    float yy  = ph[c] + 0.1f * (f - ph[c]) / tau;
                    ptv[c] = tau; pyv[c] = yy;
                    s += yy; q += yy * yy;
                }
            }
            *((float4*)(out_tau + row * H_DIM + jbase) + jj4) = tv;
            *((float4*)(g_Y + row * H_DIM + jbase) + jj4) = yv;

            s += __shfl_xor_sync(0xffffffffu, s, 1);
            q += __shfl_xor_sync(0xffffffffu, q, 1);
            s += __shfl_xor_sync(0xffffffffu, s, 2);
            q += __shfl_xor_sync(0xffffffffu, q, 2);
            s += __shfl_xor_sync(0xffffffffu, s, 4);
            q += __shfl_xor_sync(0xffffffffu, q, 4);
            s += __shfl_xor_sync(0xffffffffu, s, 8);
            q += __shfl_xor_sync(0xffffffffu, q, 8);
            if (jj4 == 0)
                g_Spart[row * 8 + bn] = make_float2(s, q);
        }
    }
}

// ---------------------------------------------------------------------------
// Finalize (verbatim): 4 rows/block, 2 float4/thread, y-loads early.
// ---------------------------------------------------------------------------
__global__ __launch_bounds__(256)
void finalize_kernel(const float* __restrict__ gamma, const float* __restrict__ beta,
                     float* __restrict__ out_h) {
    const int tid = threadIdx.x;
    const size_t row0 = (size_t)blockIdx.x * 4;
    const int r = tid >> 6;
    const int t = tid & 63;
    const size_t row = row0 + r;

    float4 ya = *((const float4*)(g_Y + row * H_DIM) + t);
    float4 yb = *((const float4*)(g_Y + row * H_DIM) + t + 64);

    __shared__ float2 mv[4];
    if (tid < 32) {
        int rr = tid >> 3, part = tid & 7;
        float2 p = g_Spart[(row0 + rr) * 8 + part];
        float s = p.x, q = p.y;
        s += __shfl_xor_sync(0xffffffffu, s, 1);
        q += __shfl_xor_sync(0xffffffffu, q, 1);
        s += __shfl_xor_sync(0xffffffffu, s, 2);
        q += __shfl_xor_sync(0xffffffffu, q, 2);
        s += __shfl_xor_sync(0xffffffffu, s, 4);
        q += __shfl_xor_sync(0xffffffffu, q, 4);
        if (part == 0) {
            float mu  = s * (1.0f / H_DIM);
            float var = q * (1.0f / H_DIM) - mu * mu;
            mv[rr] = make_float2(mu, rsqrtf(var + 1e-5f));
        }
    }
    __syncthreads();

    float mu  = mv[r].x;
    float inv = mv[r].y;

    float4 ga = ((const float4*)gamma)[t];
    float4 gb = ((const float4*)gamma)[t + 64];
    float4 ba = ((const float4*)beta)[t];
    float4 bb = ((const float4*)beta)[t + 64];

    float4 oa, ob;
    oa.x = (ya.x - mu) * inv * ga.x + ba.x;
    oa.y = (ya.y - mu) * inv * ga.y + ba.y;
    oa.z = (ya.z - mu) * inv * ga.z + ba.z;
    oa.w = (ya.w - mu) * inv * ga.w + ba.w;
    ob.x = (yb.x - mu) * inv * gb.x + bb.x;
    ob.y = (yb.y - mu) * inv * gb.y + bb.y;
    ob.z = (yb.z - mu) * inv * gb.z + bb.z;
    ob.w = (yb.w - mu) * inv * gb.w + bb.w;

    *((float4*)(out_h + row * H_DIM) + t) = oa;
    *((float4*)(out_h + row * H_DIM) + t + 64) = ob;
}

// ---------------------------------------------------------------------------
extern "C" void kernel_launch(void* const* d_in, const int* in_sizes, int n_in,
                              void* d_out, int out_size) {
    const float* x     = (const float*)d_in[0];
    const float* h     = (const float*)d_in[1];
    const float* W_in  = (const float*)d_in[2];
    const float* b_in  = (const float*)d_in[3];
    const float* W_rec = (const float*)d_in[4];
    const float* W_tau = (const float*)d_in[5];
    const float* b_tau = (const float*)d_in[6];
    const float* gamma = (const float*)d_in[7];
    const float* beta  = (const float*)d_in[8];

    const int B = in_sizes[0] / I_DIM;    // 65536

    float* out = (float*)d_out;
    float* out_h   = out;
    float* out_tau = out + (size_t)B * H_DIM;

    prep_kernel<<<B / 16 + 512, 256>>>(x, h, W_in, W_rec, W_tau);

    cudaFuncSetAttribute(gemm_mma_kernel,
                         cudaFuncAttributeMaxDynamicSharedMemorySize, SMEM_REQ);
    dim3 ggrid(NTOT / 128, B / 128);      // (8, 512)
    gemm_mma_kernel<<<ggrid, 128, SMEM_REQ>>>(h, b_in, b_tau, out_tau);

    finalize_kernel<<<B / 4, 256>>>(gamma, beta, out_h);
}